// round 8
// baseline (speedup 1.0000x reference)
#include <cuda_runtime.h>
#include <cstdint>

#define S_  16
#define A_  16
#define DA_ 128
#define DS_ 128
#define H_  64
#define TB  64
#define NTHREADS 128
#define B_MAX 2048

#define H_LD 68

// packed expert image (word offsets)
#define PK_W1 0
#define PK_W2 8192
#define PK_W3 12288
#define PK_B1 20480
#define PK_B2 20544
#define PK_B3 20608
#define PK_STRIDE 20736

// SMEM byte offsets
#define SM_W1 0                          // 8192 words fragment-order
#define SM_W2 32768                      // 4096 words
#define SM_W3 49152                      // 8192 words
#define SM_H  81920                      // [64][68] = 17408 B
#define SM_B1 99328
#define SM_B2 99584
#define SM_B3 99840
#define SMEM_BYTES 100352

__device__ int g_cnt[S_];
__device__ int g_list[S_][A_];
__device__ float    g_wpack[256 * PK_STRIDE];          // ~21.2 MB
__device__ unsigned g_acttf[(size_t)B_MAX * A_ * DA_]; // ~16.8 MB

__global__ void prep_mask_kernel(const unsigned* __restrict__ rel) {
    if (threadIdx.x != 0) return;
    bool allint = true, allfloat = true;
    for (int i = 0; i < 64; i++) {
        unsigned u = rel[i];
        if (u > 1u) allint = false;
        if (!(u == 0u || u == 0x3F800000u)) allfloat = false;
    }
    int m[S_ * A_];
    if (allint) {
        const int* p = (const int*)rel;
        for (int i = 0; i < S_ * A_; i++) m[i] = (p[i] != 0);
    } else if (allfloat) {
        const float* p = (const float*)rel;
        for (int i = 0; i < S_ * A_; i++) m[i] = (p[i] != 0.0f);
    } else {
        const unsigned char* p = (const unsigned char*)rel;
        for (int i = 0; i < S_ * A_; i++) m[i] = (p[i] != 0);
    }
    for (int s = 0; s < S_; s++) {
        int c = 0;
        for (int a = 0; a < A_; a++)
            if (m[s * A_ + a]) g_list[s][c++] = a;
        g_cnt[s] = c;
    }
}

__device__ __forceinline__ unsigned f2tf(float f) {
    unsigned u;
    asm("cvt.rna.tf32.f32 %0, %1;" : "=r"(u) : "f"(f));
    return u;
}

// Pack weights into MMA B-fragment order, converted to tf32 bits.
// Fragment layout: word idx = ((kc*NP + np)*32 + lane)*4 + (j2*2 + j)
//   element: k = kc*8 + (lane&3) + 4*j ; n = np*16 + j2*8 + (lane>>2)
__global__ void prep_wpack(const float* __restrict__ W1, const float* __restrict__ b1,
                           const float* __restrict__ W2, const float* __restrict__ b2,
                           const float* __restrict__ W3, const float* __restrict__ b3) {
    const int e = blockIdx.x;
    const int tid = threadIdx.x;
    float* dst = g_wpack + (size_t)e * PK_STRIDE;
    const float* s1 = W1 + (size_t)e * (DA_ * H_);
    const float* s2 = W2 + (size_t)e * (H_ * H_);
    const float* s3 = W3 + (size_t)e * (H_ * DS_);

    for (int idx = tid; idx < 8192; idx += 256) {          // W1: K=128, N=64 (NP=4)
        int w = idx & 3, l = (idx >> 2) & 31, g = idx >> 7;
        int kc = g >> 2, np = g & 3, j = w & 1, j2 = (w >> 1) & 1;
        int k = kc * 8 + (l & 3) + 4 * j;
        int n = np * 16 + j2 * 8 + (l >> 2);
        dst[PK_W1 + idx] = __uint_as_float(f2tf(s1[k * 64 + n]));
    }
    for (int idx = tid; idx < 4096; idx += 256) {          // W2: K=64, N=64 (NP=4)
        int w = idx & 3, l = (idx >> 2) & 31, g = idx >> 7;
        int kc = g >> 2, np = g & 3, j = w & 1, j2 = (w >> 1) & 1;
        int k = kc * 8 + (l & 3) + 4 * j;
        int n = np * 16 + j2 * 8 + (l >> 2);
        dst[PK_W2 + idx] = __uint_as_float(f2tf(s2[k * 64 + n]));
    }
    for (int idx = tid; idx < 8192; idx += 256) {          // W3: K=64, N=128 (NP=8)
        int w = idx & 3, l = (idx >> 2) & 31, g = idx >> 7;
        int kc = g >> 3, np = g & 7, j = w & 1, j2 = (w >> 1) & 1;
        int k = kc * 8 + (l & 3) + 4 * j;
        int n = np * 16 + j2 * 8 + (l >> 2);
        dst[PK_W3 + idx] = __uint_as_float(f2tf(s3[k * 128 + n]));
    }
    if (tid < 64)        dst[PK_B1 + tid]        = b1[e * H_  + tid];
    else if (tid < 128)  dst[PK_B2 + tid - 64]   = b2[e * H_  + tid - 64];
    else                 dst[PK_B3 + tid - 128]  = b3[e * DS_ + tid - 128];
}

__global__ void prep_act(const float4* __restrict__ act, int n4) {
    int i = blockIdx.x * blockDim.x + threadIdx.x;
    if (i < n4) {
        float4 v = act[i];
        uint4 u = { f2tf(v.x), f2tf(v.y), f2tf(v.z), f2tf(v.w) };
        ((uint4*)g_acttf)[i] = u;
    }
}

__device__ __forceinline__ void cpa16(uint32_t dst, const void* src) {
    asm volatile("cp.async.cg.shared.global [%0], [%1], 16;" :: "r"(dst), "l"(src));
}
#define CP_COMMIT() asm volatile("cp.async.commit_group;" ::: "memory")
#define CP_WAIT2()  asm volatile("cp.async.wait_group 2;" ::: "memory")

__device__ __forceinline__ void mma_tf32(float& d0, float& d1, float& d2, float& d3,
                                         unsigned a0, unsigned a1, unsigned a2, unsigned a3,
                                         unsigned b0, unsigned b1) {
    asm volatile(
        "mma.sync.aligned.m16n8k8.row.col.f32.tf32.tf32.f32 "
        "{%0,%1,%2,%3}, {%4,%5,%6,%7}, {%8,%9}, {%0,%1,%2,%3};"
        : "+f"(d0), "+f"(d1), "+f"(d2), "+f"(d3)
        : "r"(a0), "r"(a1), "r"(a2), "r"(a3), "r"(b0), "r"(b1));
}

// --- staging: pure linear copies from packed image ---
__device__ __forceinline__ void stage1(uint32_t sb, int tid, const float* src) {
    #pragma unroll
    for (int it = 0; it < 16; it++) {
        int i = tid + it * NTHREADS;              // 0..2047 chunks
        cpa16(sb + SM_W1 + i * 16, src + PK_W1 + i * 4);
    }
    if (tid < 16) cpa16(sb + SM_B1 + tid * 16, src + PK_B1 + tid * 4);
}
__device__ __forceinline__ void stage2(uint32_t sb, int tid, const float* src) {
    #pragma unroll
    for (int it = 0; it < 8; it++) {
        int i = tid + it * NTHREADS;              // 0..1023
        cpa16(sb + SM_W2 + i * 16, src + PK_W2 + i * 4);
    }
    if (tid < 16) cpa16(sb + SM_B2 + tid * 16, src + PK_B2 + tid * 4);
}
__device__ __forceinline__ void stage3(uint32_t sb, int tid, const float* src) {
    #pragma unroll
    for (int it = 0; it < 16; it++) {
        int i = tid + it * NTHREADS;              // 0..2047
        cpa16(sb + SM_W3 + i * 16, src + PK_W3 + i * 4);
    }
    if (tid < 32) cpa16(sb + SM_B3 + tid * 16, src + PK_B3 + tid * 4);
}

__global__ __launch_bounds__(NTHREADS, 2)
void expert_kernel(const float* __restrict__ state, float* __restrict__ out)
{
    extern __shared__ char smem[];
    const uint32_t sb = (uint32_t)__cvta_generic_to_shared(smem);
    const unsigned* W1u = (const unsigned*)(smem + SM_W1);
    const unsigned* W2u = (const unsigned*)(smem + SM_W2);
    const unsigned* W3u = (const unsigned*)(smem + SM_W3);
    float*    hs  = (float*)(smem + SM_H);
    const unsigned* hu = (const unsigned*)(smem + SM_H);
    const float* b1s = (const float*)(smem + SM_B1);
    const float* b2s = (const float*)(smem + SM_B2);
    const float* b3s = (const float*)(smem + SM_B3);

    const int s    = blockIdx.y;
    const int b0   = blockIdx.x * TB;
    const int tid  = threadIdx.x;
    const int lane = tid & 31;
    const int warp = tid >> 5;
    const int wm   = warp & 1;      // 2 warp-rows (m32)
    const int wn   = warp >> 1;     // 2 warp-cols
    const int r    = lane >> 2;
    const int q    = lane & 3;

    const int mrow0 = wm * 32 + r;

    float acc[2][8][4];
    #pragma unroll
    for (int mt = 0; mt < 2; mt++)
        #pragma unroll
        for (int nt = 0; nt < 8; nt++)
            #pragma unroll
            for (int c = 0; c < 4; c++) acc[mt][nt][c] = 0.0f;

    const int cnt = g_cnt[s];

    if (cnt > 0) {
        const float* src = g_wpack + (size_t)(s * A_ + g_list[s][0]) * PK_STRIDE;
        stage1(sb, tid, src); CP_COMMIT();
        stage2(sb, tid, src); CP_COMMIT();
        stage3(sb, tid, src); CP_COMMIT();
    }

    for (int j = 0; j < cnt; j++) {
        const int a = g_list[s][j];
        const float* srcn = (j + 1 < cnt)
            ? g_wpack + (size_t)(s * A_ + g_list[s][j + 1]) * PK_STRIDE : nullptr;

        CP_WAIT2();          // W1(j), b1(j) landed
        __syncthreads();     // publish W1; everyone done with h/W3 from prev iter

        // ---- GEMM1: h1 = relu(A @ W1 + b1), M64 N64 K128 ----
        {
            float d[2][4][4];
            #pragma unroll
            for (int mt = 0; mt < 2; mt++)
                #pragma unroll
                for (int nt = 0; nt < 4; nt++)
                    { d[mt][nt][0]=0; d[mt][nt][1]=0; d[mt][nt][2]=0; d[mt][nt][3]=0; }

            const unsigned* a0p = g_acttf + ((size_t)(b0 + mrow0) * A_ + a) * DA_ + q;
            const unsigned* a1p = a0p + (size_t)8  * A_ * DA_;
            const unsigned* a2p = a0p + (size_t)16 * A_ * DA_;
            const unsigned* a3p = a0p + (size_t)24 * A_ * DA_;

            #pragma unroll 4
            for (int kc = 0; kc < 16; kc++) {
                const int k0 = kc * 8;
                unsigned af[2][4], bf[4][2];
                af[0][0] = a0p[k0];     af[0][1] = a1p[k0];
                af[0][2] = a0p[k0 + 4]; af[0][3] = a1p[k0 + 4];
                af[1][0] = a2p[k0];     af[1][1] = a3p[k0];
                af[1][2] = a2p[k0 + 4]; af[1][3] = a3p[k0 + 4];
                uint4 p0 = *(const uint4*)(W1u + ((kc * 4 + wn * 2 + 0) * 32 + lane) * 4);
                uint4 p1 = *(const uint4*)(W1u + ((kc * 4 + wn * 2 + 1) * 32 + lane) * 4);
                bf[0][0] = p0.x; bf[0][1] = p0.y; bf[1][0] = p0.z; bf[1][1] = p0.w;
                bf[2][0] = p1.x; bf[2][1] = p1.y; bf[3][0] = p1.z; bf[3][1] = p1.w;
                #pragma unroll
                for (int mt = 0; mt < 2; mt++)
                    #pragma unroll
                    for (int nt = 0; nt < 4; nt++)
                        mma_tf32(d[mt][nt][0], d[mt][nt][1], d[mt][nt][2], d[mt][nt][3],
                                 af[mt][0], af[mt][1], af[mt][2], af[mt][3],
                                 bf[nt][0], bf[nt][1]);
            }
            #pragma unroll
            for (int mt = 0; mt < 2; mt++)
                #pragma unroll
                for (int nt = 0; nt < 4; nt++) {
                    int col = wn * 32 + nt * 8 + 2 * q;
                    float bb0 = b1s[col], bb1 = b1s[col + 1];
                    int row = mrow0 + mt * 16;
                    uint2 v0 = { f2tf(fmaxf(d[mt][nt][0] + bb0, 0.0f)),
                                 f2tf(fmaxf(d[mt][nt][1] + bb1, 0.0f)) };
                    uint2 v1 = { f2tf(fmaxf(d[mt][nt][2] + bb0, 0.0f)),
                                 f2tf(fmaxf(d[mt][nt][3] + bb1, 0.0f)) };
                    *(uint2*)(hs + row * H_LD + col)       = v0;
                    *(uint2*)(hs + (row + 8) * H_LD + col) = v1;
                }
        }
        __syncthreads();     // ALL warps done reading W1(j)/b1(j) before overwrite
        if (srcn) { stage1(sb, tid, srcn); }
        CP_COMMIT();
        CP_WAIT2();          // W2(j), b2(j) landed
        __syncthreads();     // publish W2; h1 visible to all warps

        // ---- GEMM2: h2 = relu(h1 @ W2 + b2), M64 N64 K64 (in-place h) ----
        {
            unsigned a2r[8][2][4];
            #pragma unroll
            for (int kc = 0; kc < 8; kc++) {
                const int k0 = kc * 8;
                #pragma unroll
                for (int mt = 0; mt < 2; mt++) {
                    const unsigned* hb = hu + (mrow0 + mt * 16) * H_LD + k0 + q;
                    a2r[kc][mt][0] = hb[0];
                    a2r[kc][mt][1] = hb[8 * H_LD];
                    a2r[kc][mt][2] = hb[4];
                    a2r[kc][mt][3] = hb[8 * H_LD + 4];
                }
            }
            __syncthreads();   // all reads of h1 done; safe to overwrite

            float d[2][4][4];
            #pragma unroll
            for (int mt = 0; mt < 2; mt++)
                #pragma unroll
                for (int nt = 0; nt < 4; nt++)
                    { d[mt][nt][0]=0; d[mt][nt][1]=0; d[mt][nt][2]=0; d[mt][nt][3]=0; }
            #pragma unroll
            for (int kc = 0; kc < 8; kc++) {
                unsigned bf[4][2];
                uint4 p0 = *(const uint4*)(W2u + ((kc * 4 + wn * 2 + 0) * 32 + lane) * 4);
                uint4 p1 = *(const uint4*)(W2u + ((kc * 4 + wn * 2 + 1) * 32 + lane) * 4);
                bf[0][0] = p0.x; bf[0][1] = p0.y; bf[1][0] = p0.z; bf[1][1] = p0.w;
                bf[2][0] = p1.x; bf[2][1] = p1.y; bf[3][0] = p1.z; bf[3][1] = p1.w;
                #pragma unroll
                for (int mt = 0; mt < 2; mt++)
                    #pragma unroll
                    for (int nt = 0; nt < 4; nt++)
                        mma_tf32(d[mt][nt][0], d[mt][nt][1], d[mt][nt][2], d[mt][nt][3],
                                 a2r[kc][mt][0], a2r[kc][mt][1], a2r[kc][mt][2], a2r[kc][mt][3],
                                 bf[nt][0], bf[nt][1]);
            }
            #pragma unroll
            for (int mt = 0; mt < 2; mt++)
                #pragma unroll
                for (int nt = 0; nt < 4; nt++) {
                    int col = wn * 32 + nt * 8 + 2 * q;
                    float bb0 = b2s[col], bb1 = b2s[col + 1];
                    int row = mrow0 + mt * 16;
                    uint2 v0 = { f2tf(fmaxf(d[mt][nt][0] + bb0, 0.0f)),
                                 f2tf(fmaxf(d[mt][nt][1] + bb1, 0.0f)) };
                    uint2 v1 = { f2tf(fmaxf(d[mt][nt][2] + bb0, 0.0f)),
                                 f2tf(fmaxf(d[mt][nt][3] + bb1, 0.0f)) };
                    *(uint2*)(hs + row * H_LD + col)       = v0;
                    *(uint2*)(hs + (row + 8) * H_LD + col) = v1;
                }
        }
        __syncthreads();     // ALL warps done reading W2(j)/b2(j) before overwrite
        if (srcn) { stage2(sb, tid, srcn); }
        CP_COMMIT();
        CP_WAIT2();          // W3(j), b3(j) landed
        __syncthreads();     // publish W3; h2 visible to all warps

        // ---- GEMM3: acc += relu(h2 @ W3 + b3), M64 N128 K64 ----
        {
            float d[2][8][4];
            #pragma unroll
            for (int mt = 0; mt < 2; mt++)
                #pragma unroll
                for (int nt = 0; nt < 8; nt++)
                    { d[mt][nt][0]=0; d[mt][nt][1]=0; d[mt][nt][2]=0; d[mt][nt][3]=0; }
            #pragma unroll 2
            for (int kc = 0; kc < 8; kc++) {
                const int k0 = kc * 8;
                unsigned af[2][4], bf[8][2];
                #pragma unroll
                for (int mt = 0; mt < 2; mt++) {
                    const unsigned* hb = hu + (mrow0 + mt * 16) * H_LD + k0 + q;
                    af[mt][0] = hb[0];
                    af[mt][1] = hb[8 * H_LD];
                    af[mt][2] = hb[4];
                    af[mt][3] = hb[8 * H_LD + 4];
                }
                #pragma unroll
                for (int pp = 0; pp < 4; pp++) {
                    uint4 p = *(const uint4*)(W3u + ((kc * 8 + wn * 4 + pp) * 32 + lane) * 4);
                    bf[2 * pp][0]     = p.x; bf[2 * pp][1]     = p.y;
                    bf[2 * pp + 1][0] = p.z; bf[2 * pp + 1][1] = p.w;
                }
                #pragma unroll
                for (int mt = 0; mt < 2; mt++)
                    #pragma unroll
                    for (int nt = 0; nt < 8; nt++)
                        mma_tf32(d[mt][nt][0], d[mt][nt][1], d[mt][nt][2], d[mt][nt][3],
                                 af[mt][0], af[mt][1], af[mt][2], af[mt][3],
                                 bf[nt][0], bf[nt][1]);
            }
            #pragma unroll
            for (int mt = 0; mt < 2; mt++)
                #pragma unroll
                for (int nt = 0; nt < 8; nt++) {
                    int col = wn * 64 + nt * 8 + 2 * q;
                    float bb0 = b3s[col], bb1 = b3s[col + 1];
                    acc[mt][nt][0] += fmaxf(d[mt][nt][0] + bb0, 0.0f);
                    acc[mt][nt][1] += fmaxf(d[mt][nt][1] + bb1, 0.0f);
                    acc[mt][nt][2] += fmaxf(d[mt][nt][2] + bb0, 0.0f);
                    acc[mt][nt][3] += fmaxf(d[mt][nt][3] + bb1, 0.0f);
                }
        }
        __syncthreads();     // ALL warps done reading W3(j)/b3(j)/h2 before overwrite
        if (srcn) { stage3(sb, tid, srcn); }
        CP_COMMIT();
    }

    // ---- epilogue: out = state + diff ----
    #pragma unroll
    for (int mt = 0; mt < 2; mt++)
        #pragma unroll
        for (int nt = 0; nt < 8; nt++) {
            int row = b0 + mrow0 + mt * 16;
            int col = wn * 64 + nt * 8 + 2 * q;
            size_t base = ((size_t)row * S_ + s) * DS_ + col;
            float2 s0 = *(const float2*)(state + base);
            float2 s1 = *(const float2*)(state + base + 8 * (size_t)S_ * DS_);
            float2 o0 = { s0.x + acc[mt][nt][0], s0.y + acc[mt][nt][1] };
            float2 o1 = { s1.x + acc[mt][nt][2], s1.y + acc[mt][nt][3] };
            *(float2*)(out + base)                        = o0;
            *(float2*)(out + base + 8 * (size_t)S_ * DS_) = o1;
        }
}

extern "C" void kernel_launch(void* const* d_in, const int* in_sizes, int n_in,
                              void* d_out, int out_size)
{
    const float* state = (const float*)d_in[0];
    const float* act   = (const float*)d_in[1];
    const void*  rel   = d_in[2];
    const float* W1 = (const float*)d_in[3];
    const float* b1 = (const float*)d_in[4];
    const float* W2 = (const float*)d_in[5];
    const float* b2 = (const float*)d_in[6];
    const float* W3 = (const float*)d_in[7];
    const float* b3 = (const float*)d_in[8];
    float* out = (float*)d_out;

    const int B = in_sizes[0] / (S_ * DS_);

    cudaFuncSetAttribute(expert_kernel,
                         cudaFuncAttributeMaxDynamicSharedMemorySize, SMEM_BYTES);

    prep_mask_kernel<<<1, 32>>>((const unsigned*)rel);
    prep_wpack<<<S_ * A_, 256>>>(W1, b1, W2, b2, W3, b3);
    {
        int n4 = B * A_ * DA_ / 4;
        prep_act<<<(n4 + 255) / 256, 256>>>((const float4*)act, n4);
    }

    dim3 grid(B / TB, S_);
    expert_kernel<<<grid, NTHREADS, SMEM_BYTES>>>(state, out);
}